// round 4
// baseline (speedup 1.0000x reference)
#include <cuda_runtime.h>
#include <cstdint>

// Problem constants
static constexpr int N_ = 1024;
static constexpr int K_ = 32;
static constexpr int I_ = 10000;
static constexpr int I4_ = I_ / 4;       // 2500 float4 chunks per row
static constexpr int WPB = 8;            // warps per block (8 k's per block)
static constexpr int KG  = K_ / WPB;     // 4 k-groups per n

__device__ __forceinline__ float lg2_approx(float v) {
    float r; asm("lg2.approx.f32 %0, %1;" : "=f"(r) : "f"(v)); return r;
}
__device__ __forceinline__ float ex2_approx(float v) {
    float r; asm("ex2.approx.f32 %0, %1;" : "=f"(r) : "f"(v)); return r;
}
// f32x2 packed helpers (sm_103a FFMA2 path — ptxas never emits these from C++)
__device__ __forceinline__ uint64_t pk(float lo, float hi) {
    uint64_t r; asm("mov.b64 %0, {%1, %2};" : "=l"(r) : "f"(lo), "f"(hi)); return r;
}
__device__ __forceinline__ void upk(uint64_t v, float& lo, float& hi) {
    asm("mov.b64 {%0, %1}, %2;" : "=f"(lo), "=f"(hi) : "l"(v));
}
__device__ __forceinline__ uint64_t fma2(uint64_t a, uint64_t b, uint64_t c) {
    uint64_t d; asm("fma.rn.f32x2 %0, %1, %2, %3;" : "=l"(d) : "l"(a), "l"(b), "l"(c)); return d;
}
__device__ __forceinline__ uint64_t add2(uint64_t a, uint64_t b) {
    uint64_t d; asm("add.rn.f32x2 %0, %1, %2;" : "=l"(d) : "l"(a), "l"(b)); return d;
}

// out[n,k] = (sum_i x*w) / (sum_i w),   w = 2^( cs*logits - 0.1*log2(t) ),
// t = -ln(u).  With L = lg2(u):  log2(t) = log2(-L) + log2(ln2).
// log2(-L) = (bits(-L)*2^-23 - 127) + D(m);  D approximated by a degree-5
// poly in mantissa m, coefficients pre-scaled by -0.1 (1/temp in log2 space).
// FMNMX clamp guards lg2.approx underflow to +/-0 at u -> 1.
//
// Occupancy strategy: 256-thread blocks (8 warps = 8 k's), 4 blocks per n.
// 5 CTAs/SM x 40KB smem = 200KB, 1280 threads, regs capped at 51 => 40
// resident warps/SM (vs 32 with 1024-thread blocks), raising outstanding
// DRAM loads by +25%. This kernel is memory-latency x MLP bound.
__global__ void __launch_bounds__(256, 5)
concrete_selector_kernel(const float* __restrict__ x,
                         const float* __restrict__ u,
                         const float* __restrict__ logits,
                         float* __restrict__ out) {
    __shared__ __align__(16) float xs[I_];   // full x row for this n (40000 B)

    const int bid = blockIdx.x;
    const int n   = bid >> 2;        // 4 blocks per n
    const int kg  = bid & 3;         // k-group 0..3
    const int tid = threadIdx.x;

    // Cooperative load of x[n, :] into shared (float4)
    {
        const float4* __restrict__ xg4 =
            reinterpret_cast<const float4*>(x + (size_t)n * I_);
        float4* xs4 = reinterpret_cast<float4*>(xs);
        for (int i = tid; i < I4_; i += 256) xs4[i] = xg4[i];
    }
    __syncthreads();

    const int warp = tid >> 5;       // 0..7
    const int lane = tid & 31;
    const int k    = kg * WPB + warp;

    const float4* __restrict__ ug4 =
        reinterpret_cast<const float4*>(u + ((size_t)n * K_ + k) * (size_t)I_);
    const float4* __restrict__ cg4 =
        reinterpret_cast<const float4*>(logits + (size_t)k * I_);
    const uint64_t* __restrict__ xs2 = reinterpret_cast<const uint64_t*>(xs);

    // Packed constants (splat)
    const uint64_t G5 = pk(-4.32743e-3f,  -4.32743e-3f);
    const uint64_t G4 = pk( 4.044865e-2f,  4.044865e-2f);
    const uint64_t G3 = pk(-1.595078e-1f, -1.595078e-1f);
    const uint64_t G2 = pk( 3.497547e-1f,  3.497547e-1f);
    const uint64_t G1 = pk(-4.0528685e-1f,-4.0528685e-1f);
    const uint64_t CH = pk(-1.1920929e-8f,-1.1920929e-8f);  // -0.1 * 2^-23
    const uint64_t CB = pk( 1.29317951e1f, 1.29317951e1f);  // 12.7+g0-0.1*log2(ln2)
    const uint64_t CS = pk( 4.3280850e-1f, 4.3280850e-1f);  // 3/(10*ln2)

    uint64_t accA2 = 0;   // packed pair of partial sums of x*w
    uint64_t accB2 = 0;   // packed pair of partial sums of w

    auto pbody = [&](float u0, float u1, float l0, float l1, uint64_t xp) {
        float L0 = lg2_approx(u0);                 // MUFU (u<1 -> L<0)
        float L1 = lg2_approx(u1);
        int   b0 = __float_as_int(L0);
        int   b1 = __float_as_int(L1);
        float m0 = __int_as_float((b0 & 0x007fffff) | 0x3f800000);  // LOP3
        float m1 = __int_as_float((b1 & 0x007fffff) | 0x3f800000);
        float c0 = (float)(b0 & 0x7fffffff);       // LOP3 + I2F: bits of -L
        float c1 = (float)(b1 & 0x7fffffff);
        c0 = fmaxf(c0, 8.4e8f);                    // clamp: lg2 underflow guard
        c1 = fmaxf(c1, 8.4e8f);
        uint64_t mp = pk(m0, m1);
        uint64_t cp = pk(c0, c1);
        uint64_t lp = pk(l0, l1);
        uint64_t r  = fma2(mp, G5, G4);
        r           = fma2(mp, r, G3);
        r           = fma2(mp, r, G2);
        r           = fma2(mp, r, G1);
        uint64_t hb = fma2(cp, CH, CB);
        uint64_t sv = fma2(lp, CS, hb);
        uint64_t s2 = fma2(mp, r, sv);             // full log2-score (pair)
        float sa, sb; upk(s2, sa, sb);
        uint64_t wp = pk(ex2_approx(sa), ex2_approx(sb));   // MUFU x2
        accB2 = add2(accB2, wp);
        accA2 = fma2(xp, wp, accA2);
    };

    constexpr int MAIN = (I4_ / 32) * 32;   // 2496: uniform main loop
    #pragma unroll 2
    for (int j = lane; j < MAIN; j += 32) {
        float4 uu = __ldcs(&ug4[j]);   // streaming: protect L2 for logits/x
        float4 cc = cg4[j];
        uint64_t xlo = xs2[2 * j];
        uint64_t xhi = xs2[2 * j + 1];
        pbody(uu.x, uu.y, cc.x, cc.y, xlo);
        pbody(uu.z, uu.w, cc.z, cc.w, xhi);
    }
    // Tail: chunks 2496..2499 handled by lanes 0..3
    if (lane < I4_ - MAIN) {
        int j = MAIN + lane;
        float4 uu = __ldcs(&ug4[j]);
        float4 cc = cg4[j];
        uint64_t xlo = xs2[2 * j];
        uint64_t xhi = xs2[2 * j + 1];
        pbody(uu.x, uu.y, cc.x, cc.y, xlo);
        pbody(uu.z, uu.w, cc.z, cc.w, xhi);
    }

    // Collapse packed accumulators, then warp reduction
    float a0, a1, bb0, bb1;
    upk(accA2, a0, a1);
    upk(accB2, bb0, bb1);
    float accA = a0 + a1;
    float accB = bb0 + bb1;
    #pragma unroll
    for (int off = 16; off > 0; off >>= 1) {
        accA += __shfl_down_sync(0xffffffffu, accA, off);
        accB += __shfl_down_sync(0xffffffffu, accB, off);
    }
    if (lane == 0) {
        out[(size_t)n * K_ + k] = accA / accB;
    }
}

extern "C" void kernel_launch(void* const* d_in, const int* in_sizes, int n_in,
                              void* d_out, int out_size) {
    const float* x      = (const float*)d_in[0];   // (1024, 10000)
    const float* u      = (const float*)d_in[1];   // (1024, 32, 10000)
    const float* logits = (const float*)d_in[2];   // (32, 10000)
    float* out = (float*)d_out;                    // (1024, 32)
    (void)in_sizes; (void)n_in; (void)out_size;

    concrete_selector_kernel<<<N_ * KG, 256>>>(x, u, logits, out);
}

// round 5
// speedup vs baseline: 1.5382x; 1.5382x over previous
#include <cuda_runtime.h>
#include <cstdint>

// Problem constants
static constexpr int N_ = 1024;
static constexpr int K_ = 32;
static constexpr int I_ = 10000;
static constexpr int I4_ = I_ / 4;       // 2500 float4 chunks per row

__device__ __forceinline__ float lg2_approx(float v) {
    float r; asm("lg2.approx.f32 %0, %1;" : "=f"(r) : "f"(v)); return r;
}
__device__ __forceinline__ float ex2_approx(float v) {
    float r; asm("ex2.approx.f32 %0, %1;" : "=f"(r) : "f"(v)); return r;
}
// f32x2 packed helpers (sm_103a FFMA2 path — ptxas never emits these from C++)
__device__ __forceinline__ uint64_t pk(float lo, float hi) {
    uint64_t r; asm("mov.b64 %0, {%1, %2};" : "=l"(r) : "f"(lo), "f"(hi)); return r;
}
__device__ __forceinline__ void upk(uint64_t v, float& lo, float& hi) {
    asm("mov.b64 {%0, %1}, %2;" : "=f"(lo), "=f"(hi) : "l"(v));
}
__device__ __forceinline__ uint64_t fma2(uint64_t a, uint64_t b, uint64_t c) {
    uint64_t d; asm("fma.rn.f32x2 %0, %1, %2, %3;" : "=l"(d) : "l"(a), "l"(b), "l"(c)); return d;
}
__device__ __forceinline__ uint64_t add2(uint64_t a, uint64_t b) {
    uint64_t d; asm("add.rn.f32x2 %0, %1, %2;" : "=l"(d) : "l"(a), "l"(b)); return d;
}

// out[n,k] = (sum_i x*w) / (sum_i w),   w = 2^( cs*logits - 0.1*log2(t) ),
// t = -ln(u).  With L = lg2(u):  log2(t) = log2(-L) + log2(ln2).
// log2(-L) = (bits(-L)*2^-23 - 127) + D(m);  D approximated by a degree-5
// poly in mantissa m, coefficients pre-scaled by -0.1 (1/temp in log2 space).
// FMNMX clamp guards lg2.approx underflow to +/-0 at u -> 1.
//
// Layout: mode-W (1 CTA x 1024 threads per SM; multi-CTA layouts measurably
// suffer cross-CTA L1tex-queue spread on B300). The main loop is explicitly
// software-pipelined with prefetch depth 2: iteration `it` issues the LDG.128s
// for it+2 before computing it, so each warp keeps ~4 loads in flight instead
// of <1 (the kernel is DRAM-latency x MLP bound).
__global__ void __launch_bounds__(1024, 1)
concrete_selector_kernel(const float* __restrict__ x,
                         const float* __restrict__ u,
                         const float* __restrict__ logits,
                         float* __restrict__ out) {
    __shared__ __align__(16) float xs[I_];   // x row for this n (40000 B)

    const int n   = blockIdx.x;
    const int tid = threadIdx.x;

    // Cooperative load of x[n, :] into shared (float4)
    {
        const float4* __restrict__ xg4 =
            reinterpret_cast<const float4*>(x + (size_t)n * I_);
        float4* xs4 = reinterpret_cast<float4*>(xs);
        for (int i = tid; i < I4_; i += 1024) xs4[i] = xg4[i];
    }
    __syncthreads();

    const int warp = tid >> 5;
    const int lane = tid & 31;
    const int k    = warp;    // 32 warps == 32 k's

    const float4* __restrict__ ug4 =
        reinterpret_cast<const float4*>(u + ((size_t)n * K_ + k) * (size_t)I_);
    const float4* __restrict__ cg4 =
        reinterpret_cast<const float4*>(logits + (size_t)k * I_);
    const uint64_t* __restrict__ xs2 = reinterpret_cast<const uint64_t*>(xs);

    // Packed poly constants (splat). hb/sv constants stay as FFMA immediates.
    const uint64_t G5 = pk(-4.32743e-3f,  -4.32743e-3f);
    const uint64_t G4 = pk( 4.044865e-2f,  4.044865e-2f);
    const uint64_t G3 = pk(-1.595078e-1f, -1.595078e-1f);
    const uint64_t G2 = pk( 3.497547e-1f,  3.497547e-1f);
    const uint64_t G1 = pk(-4.0528685e-1f,-4.0528685e-1f);

    uint64_t accA2 = 0;   // packed pair of partial sums of x*w
    uint64_t accB2 = 0;   // packed pair of partial sums of w

    auto pbody = [&](float u0, float u1, float l0, float l1, uint64_t xp) {
        float L0 = lg2_approx(u0);                 // MUFU (u<1 -> L<0)
        float L1 = lg2_approx(u1);
        int   b0 = __float_as_int(L0);
        int   b1 = __float_as_int(L1);
        float m0 = __int_as_float((b0 & 0x007fffff) | 0x3f800000);  // LOP3
        float m1 = __int_as_float((b1 & 0x007fffff) | 0x3f800000);
        float c0 = (float)(b0 & 0x7fffffff);       // LOP3 + I2F: bits of -L
        float c1 = (float)(b1 & 0x7fffffff);
        c0 = fmaxf(c0, 8.4e8f);                    // clamp: lg2 underflow guard
        c1 = fmaxf(c1, 8.4e8f);
        // hb = -0.1*2^-23 * bits + (12.7 + g0 - 0.1*log2(ln2)) ; scalar FFMA-imm
        float hb0 = fmaf(c0, -1.1920929e-8f, 12.9317951f);
        float hb1 = fmaf(c1, -1.1920929e-8f, 12.9317951f);
        float sv0 = fmaf(l0, 0.43280850f, hb0);    // + (3/(10 ln2))*logits
        float sv1 = fmaf(l1, 0.43280850f, hb1);
        uint64_t mp = pk(m0, m1);
        uint64_t sv = pk(sv0, sv1);
        uint64_t r  = fma2(mp, G5, G4);
        r           = fma2(mp, r, G3);
        r           = fma2(mp, r, G2);
        r           = fma2(mp, r, G1);
        uint64_t s2 = fma2(mp, r, sv);             // full log2-score (pair)
        float sa, sb; upk(s2, sa, sb);
        uint64_t wp = pk(ex2_approx(sa), ex2_approx(sb));   // MUFU x2
        accB2 = add2(accB2, wp);
        accA2 = fma2(xp, wp, accA2);
    };

    // 78 full iterations per warp (j = lane + 32*it, covering chunks 0..2495),
    // software-pipelined with prefetch depth 2.
    float4 A0 = __ldcs(&ug4[lane]);
    float4 C0 = cg4[lane];
    float4 A1 = __ldcs(&ug4[lane + 32]);
    float4 C1 = cg4[lane + 32];
    int j = lane;
    #pragma unroll 2
    for (int it = 0; it < 76; ++it) {
        float4 An = __ldcs(&ug4[j + 64]);   // prefetch it+2 (issues ~150cyc early)
        float4 Cn = cg4[j + 64];
        uint64_t xlo = xs2[2 * j];
        uint64_t xhi = xs2[2 * j + 1];
        pbody(A0.x, A0.y, C0.x, C0.y, xlo);
        pbody(A0.z, A0.w, C0.z, C0.w, xhi);
        A0 = A1; C0 = C1; A1 = An; C1 = Cn;
        j += 32;
    }
    // Pipeline epilogue: consume the two buffered iterations
    {
        uint64_t xlo = xs2[2 * j];
        uint64_t xhi = xs2[2 * j + 1];
        pbody(A0.x, A0.y, C0.x, C0.y, xlo);
        pbody(A0.z, A0.w, C0.z, C0.w, xhi);
        j += 32;
        xlo = xs2[2 * j];
        xhi = xs2[2 * j + 1];
        pbody(A1.x, A1.y, C1.x, C1.y, xlo);
        pbody(A1.z, A1.w, C1.z, C1.w, xhi);
    }
    // Tail: chunks 2496..2499 handled by lanes 0..3
    if (lane < I4_ - 2496) {
        int jt = 2496 + lane;
        float4 uu = __ldcs(&ug4[jt]);
        float4 cc = cg4[jt];
        uint64_t xlo = xs2[2 * jt];
        uint64_t xhi = xs2[2 * jt + 1];
        pbody(uu.x, uu.y, cc.x, cc.y, xlo);
        pbody(uu.z, uu.w, cc.z, cc.w, xhi);
    }

    // Collapse packed accumulators, then warp reduction
    float a0, a1, bb0, bb1;
    upk(accA2, a0, a1);
    upk(accB2, bb0, bb1);
    float accA = a0 + a1;
    float accB = bb0 + bb1;
    #pragma unroll
    for (int off = 16; off > 0; off >>= 1) {
        accA += __shfl_down_sync(0xffffffffu, accA, off);
        accB += __shfl_down_sync(0xffffffffu, accB, off);
    }
    if (lane == 0) {
        out[(size_t)n * K_ + k] = accA / accB;
    }
}

extern "C" void kernel_launch(void* const* d_in, const int* in_sizes, int n_in,
                              void* d_out, int out_size) {
    const float* x      = (const float*)d_in[0];   // (1024, 10000)
    const float* u      = (const float*)d_in[1];   // (1024, 32, 10000)
    const float* logits = (const float*)d_in[2];   // (32, 10000)
    float* out = (float*)d_out;                    // (1024, 32)
    (void)in_sizes; (void)n_in; (void)out_size;

    concrete_selector_kernel<<<N_, 1024>>>(x, u, logits, out);
}

// round 6
// speedup vs baseline: 1.6851x; 1.0955x over previous
#include <cuda_runtime.h>
#include <cstdint>

// Problem constants
static constexpr int N_ = 1024;
static constexpr int K_ = 32;
static constexpr int I_ = 10000;
static constexpr int I4_ = I_ / 4;       // 2500 float4 chunks per row

__device__ __forceinline__ float lg2_approx(float v) {
    float r; asm("lg2.approx.f32 %0, %1;" : "=f"(r) : "f"(v)); return r;
}
__device__ __forceinline__ float ex2_approx(float v) {
    float r; asm("ex2.approx.f32 %0, %1;" : "=f"(r) : "f"(v)); return r;
}
// f32x2 packed helpers (sm_103a FFMA2 path — ptxas never emits these from C++)
__device__ __forceinline__ uint64_t pk(float lo, float hi) {
    uint64_t r; asm("mov.b64 %0, {%1, %2};" : "=l"(r) : "f"(lo), "f"(hi)); return r;
}
__device__ __forceinline__ void upk(uint64_t v, float& lo, float& hi) {
    asm("mov.b64 {%0, %1}, %2;" : "=f"(lo), "=f"(hi) : "l"(v));
}
__device__ __forceinline__ uint64_t fma2(uint64_t a, uint64_t b, uint64_t c) {
    uint64_t d; asm("fma.rn.f32x2 %0, %1, %2, %3;" : "=l"(d) : "l"(a), "l"(b), "l"(c)); return d;
}
__device__ __forceinline__ uint64_t add2(uint64_t a, uint64_t b) {
    uint64_t d; asm("add.rn.f32x2 %0, %1, %2;" : "=l"(d) : "l"(a), "l"(b)); return d;
}

// out[n,k] = (sum_i x*w) / (sum_i w),   w = 2^( cs*logits - 0.1*log2(t) ),
// t = -ln(u).  With L = lg2(u):  log2(t) = log2(-L) + log2(ln2).
//
// Signed-bits trick: for L<0, ti = bits(L) as SIGNED int = bits(-L) - 2^31,
// so  -0.1*(bits(-L)*2^-23 - 127) folds to  ti*(-0.1*2^-23) + (12.7 - 25.6).
// No abs-mask LOP3 needed. Mantissa poly (deg-4, Chebyshev nodes on [1,2])
// approximates -0.1*(log2 m - (m-1)); H0 + (-0.1)*log2(ln2) folded into the
// FFMA base constant: -12.6972864 = 12.7 - 25.6 + 0.1498370 + 0.0528766.
// FMNMX clamp (ti >= 8.4e8 - 2^31) guards lg2.approx underflow at u -> 1.
//
// Layout: mode-W (1 CTA x 1024 threads/SM — multi-CTA layouts suffer
// cross-CTA L1tex-queue spread on B300), software-pipelined prefetch depth 2.
__global__ void __launch_bounds__(1024, 1)
concrete_selector_kernel(const float* __restrict__ x,
                         const float* __restrict__ u,
                         const float* __restrict__ logits,
                         float* __restrict__ out) {
    __shared__ __align__(16) float xs[I_];   // x row for this n (40000 B)

    const int n   = blockIdx.x;
    const int tid = threadIdx.x;

    // Cooperative load of x[n, :] into shared (float4)
    {
        const float4* __restrict__ xg4 =
            reinterpret_cast<const float4*>(x + (size_t)n * I_);
        float4* xs4 = reinterpret_cast<float4*>(xs);
        for (int i = tid; i < I4_; i += 1024) xs4[i] = xg4[i];
    }
    __syncthreads();

    const int warp = tid >> 5;
    const int lane = tid & 31;
    const int k    = warp;    // 32 warps == 32 k's

    const float4* __restrict__ ug4 =
        reinterpret_cast<const float4*>(u + ((size_t)n * K_ + k) * (size_t)I_);
    const float4* __restrict__ cg4 =
        reinterpret_cast<const float4*>(logits + (size_t)k * I_);
    const ulonglong2* __restrict__ xsv =
        reinterpret_cast<const ulonglong2*>(xs);   // LDS.128 -> two packed pairs

    // Packed deg-4 poly constants: -0.1*(log2 m - (m-1)) = H4 m^4 + ... + H0
    const uint64_t G4 = pk( 7.8445e-3f,    7.8445e-3f);
    const uint64_t G3 = pk(-6.26053e-2f,  -6.26053e-2f);
    const uint64_t G2 = pk( 2.078377e-1f,  2.078377e-1f);
    const uint64_t G1 = pk(-3.029252e-1f, -3.029252e-1f);

    uint64_t accA2 = 0;   // packed pair of partial sums of x*w
    uint64_t accB2 = 0;   // packed pair of partial sums of w

    auto pbody = [&](float u0, float u1, float l0, float l1, uint64_t xp) {
        float L0 = lg2_approx(u0);                 // MUFU (u<1 -> L<0)
        float L1 = lg2_approx(u1);
        int   b0 = __float_as_int(L0);
        int   b1 = __float_as_int(L1);
        float m0 = __int_as_float((b0 & 0x007fffff) | 0x3f800000);  // LOP3
        float m1 = __int_as_float((b1 & 0x007fffff) | 0x3f800000);
        float c0 = (float)b0;                      // I2F.S32 (signed-bits trick)
        float c1 = (float)b1;
        c0 = fmaxf(c0, -1.30748365e9f);            // clamp: lg2 underflow guard
        c1 = fmaxf(c1, -1.30748365e9f);
        float hb0 = fmaf(c0, -1.1920929e-8f, -12.6972864f);   // FFMA-imm
        float hb1 = fmaf(c1, -1.1920929e-8f, -12.6972864f);
        float sv0 = fmaf(l0, 0.43280850f, hb0);    // + (3/(10 ln2))*logits
        float sv1 = fmaf(l1, 0.43280850f, hb1);
        uint64_t mp = pk(m0, m1);
        uint64_t sv = pk(sv0, sv1);
        uint64_t r  = fma2(mp, G4, G3);
        r           = fma2(mp, r, G2);
        r           = fma2(mp, r, G1);
        uint64_t s2 = fma2(mp, r, sv);             // full log2-score (pair)
        float sa, sb; upk(s2, sa, sb);
        uint64_t wp = pk(ex2_approx(sa), ex2_approx(sb));   // MUFU x2
        accB2 = add2(accB2, wp);
        accA2 = fma2(xp, wp, accA2);
    };

    // 78 full iterations per warp (chunks 0..2495), prefetch depth 2.
    float4 A0 = __ldcs(&ug4[lane]);
    float4 C0 = cg4[lane];
    float4 A1 = __ldcs(&ug4[lane + 32]);
    float4 C1 = cg4[lane + 32];
    int j = lane;
    #pragma unroll 2
    for (int it = 0; it < 76; ++it) {
        float4 An = __ldcs(&ug4[j + 64]);   // prefetch it+2 (~150cyc early)
        float4 Cn = cg4[j + 64];
        ulonglong2 X = xsv[j];              // one LDS.128: both packed pairs
        pbody(A0.x, A0.y, C0.x, C0.y, X.x);
        pbody(A0.z, A0.w, C0.z, C0.w, X.y);
        A0 = A1; C0 = C1; A1 = An; C1 = Cn;
        j += 32;
    }
    // Pipeline epilogue: consume the two buffered iterations
    {
        ulonglong2 X = xsv[j];
        pbody(A0.x, A0.y, C0.x, C0.y, X.x);
        pbody(A0.z, A0.w, C0.z, C0.w, X.y);
        j += 32;
        X = xsv[j];
        pbody(A1.x, A1.y, C1.x, C1.y, X.x);
        pbody(A1.z, A1.w, C1.z, C1.w, X.y);
    }
    // Tail: chunks 2496..2499 handled by lanes 0..3
    if (lane < I4_ - 2496) {
        int jt = 2496 + lane;
        float4 uu = __ldcs(&ug4[jt]);
        float4 cc = cg4[jt];
        ulonglong2 X = xsv[jt];
        pbody(uu.x, uu.y, cc.x, cc.y, X.x);
        pbody(uu.z, uu.w, cc.z, cc.w, X.y);
    }

    // Collapse packed accumulators, then warp reduction
    float a0, a1, bb0, bb1;
    upk(accA2, a0, a1);
    upk(accB2, bb0, bb1);
    float accA = a0 + a1;
    float accB = bb0 + bb1;
    #pragma unroll
    for (int off = 16; off > 0; off >>= 1) {
        accA += __shfl_down_sync(0xffffffffu, accA, off);
        accB += __shfl_down_sync(0xffffffffu, accB, off);
    }
    if (lane == 0) {
        out[(size_t)n * K_ + k] = accA / accB;
    }
}

extern "C" void kernel_launch(void* const* d_in, const int* in_sizes, int n_in,
                              void* d_out, int out_size) {
    const float* x      = (const float*)d_in[0];   // (1024, 10000)
    const float* u      = (const float*)d_in[1];   // (1024, 32, 10000)
    const float* logits = (const float*)d_in[2];   // (32, 10000)
    float* out = (float*)d_out;                    // (1024, 32)
    (void)in_sizes; (void)n_in; (void)out_size;

    concrete_selector_kernel<<<N_, 1024>>>(x, u, logits, out);
}

// round 7
// speedup vs baseline: 1.6998x; 1.0087x over previous
#include <cuda_runtime.h>
#include <cstdint>

// Problem constants
static constexpr int N_ = 1024;
static constexpr int K_ = 32;
static constexpr int I_ = 10000;
static constexpr int I4_ = I_ / 4;       // 2500 float4 chunks per row

static constexpr float CS_  = 0.43280850f;     // 3/(10*ln2)
static constexpr float CB2_ = -12.7335726f;    // 12.7-25.6-0.1*log2(ln2)+H0(deg3)

// Precomputed per-(k,i) score base: sc = CS*logits + CB2  (1.28 MB, L2-resident)
__device__ float g_sc[K_ * I_];

__device__ __forceinline__ float lg2_approx(float v) {
    float r; asm("lg2.approx.f32 %0, %1;" : "=f"(r) : "f"(v)); return r;
}
__device__ __forceinline__ float ex2_approx(float v) {
    float r; asm("ex2.approx.f32 %0, %1;" : "=f"(r) : "f"(v)); return r;
}
// f32x2 packed helpers (sm_103a FFMA2 path — ptxas never emits these from C++)
__device__ __forceinline__ uint64_t pk(float lo, float hi) {
    uint64_t r; asm("mov.b64 %0, {%1, %2};" : "=l"(r) : "f"(lo), "f"(hi)); return r;
}
__device__ __forceinline__ void upk(uint64_t v, float& lo, float& hi) {
    asm("mov.b64 {%0, %1}, %2;" : "=f"(lo), "=f"(hi) : "l"(v));
}
__device__ __forceinline__ uint64_t fma2(uint64_t a, uint64_t b, uint64_t c) {
    uint64_t d; asm("fma.rn.f32x2 %0, %1, %2, %3;" : "=l"(d) : "l"(a), "l"(b), "l"(c)); return d;
}

__global__ void precompute_sc_kernel(const float* __restrict__ logits) {
    int i = blockIdx.x * blockDim.x + threadIdx.x;
    if (i < (K_ * I_) / 4) {
        float4 v = reinterpret_cast<const float4*>(logits)[i];
        v.x = fmaf(v.x, CS_, CB2_);
        v.y = fmaf(v.y, CS_, CB2_);
        v.z = fmaf(v.z, CS_, CB2_);
        v.w = fmaf(v.w, CS_, CB2_);
        reinterpret_cast<float4*>(g_sc)[i] = v;
    }
}

// out[n,k] = (sum_i x*w) / (sum_i w),   w = 2^( sc + gumbel-term ),
// gumbel-term = -0.1*log2(-ln u) - 0.1*log2(ln2), derived from L = lg2(u):
//   signed-bits trick: ti = bits(L) (L<0) = bits(-L) - 2^31, so the exponent
//   part folds to ti*(-0.1*2^-23) + const; mantissa correction is a degree-3
//   poly (Chebyshev-node interp on [1,2], pre-scaled by -0.1):
//   H3 m^3 + H2 m^2 + H1 m (+H0 folded into CB2 inside g_sc).
// FMNMX clamp (ti >= -1.30748365e9) guards lg2.approx underflow at u -> 1.
//
// Layout: mode-W (1 CTA x 1024 threads/SM), software-pipelined prefetch
// depth 2. Only the poly runs packed (FFMA2); everything else is scalar to
// avoid pack/unpack MOV overhead on the issue port.
__global__ void __launch_bounds__(1024, 1)
concrete_selector_kernel(const float* __restrict__ x,
                         const float* __restrict__ u,
                         float* __restrict__ out) {
    __shared__ __align__(16) float xs[I_];   // x row for this n (40000 B)

    const int n   = blockIdx.x;
    const int tid = threadIdx.x;

    // Cooperative load of x[n, :] into shared (float4)
    {
        const float4* __restrict__ xg4 =
            reinterpret_cast<const float4*>(x + (size_t)n * I_);
        float4* xs4 = reinterpret_cast<float4*>(xs);
        for (int i = tid; i < I4_; i += 1024) xs4[i] = xg4[i];
    }
    __syncthreads();

    const int warp = tid >> 5;
    const int lane = tid & 31;
    const int k    = warp;    // 32 warps == 32 k's

    const float4* __restrict__ ug4 =
        reinterpret_cast<const float4*>(u + ((size_t)n * K_ + k) * (size_t)I_);
    const float4* __restrict__ cg4 =
        reinterpret_cast<const float4*>(g_sc + (size_t)k * I_);
    const float4* __restrict__ xs4 = reinterpret_cast<const float4*>(xs);

    // Packed deg-3 poly constants: -0.1*(log2 m - (m-1)) ~= H3 m^3+H2 m^2+H1 m+H0
    const uint64_t H3 = pk(-1.52368e-2f,  -1.52368e-2f);
    const uint64_t H2 = pk( 1.025445e-1f,  1.025445e-1f);
    const uint64_t H1 = pk(-2.009419e-1f, -2.009419e-1f);

    float aA0 = 0.0f, aA1 = 0.0f;   // scalar partial sums of x*w
    float aB0 = 0.0f, aB1 = 0.0f;   // scalar partial sums of w

    auto pbody = [&](float u0, float u1, float sc0, float sc1, float x0, float x1) {
        float L0 = lg2_approx(u0);                 // MUFU (u<1 -> L<0)
        float L1 = lg2_approx(u1);
        int   b0 = __float_as_int(L0);
        int   b1 = __float_as_int(L1);
        float m0 = __int_as_float((b0 & 0x007fffff) | 0x3f800000);  // LOP3
        float m1 = __int_as_float((b1 & 0x007fffff) | 0x3f800000);
        float c0 = (float)b0;                      // I2F.S32 (signed-bits trick)
        float c1 = (float)b1;
        c0 = fmaxf(c0, -1.30748365e9f);            // clamp: lg2 underflow guard
        c1 = fmaxf(c1, -1.30748365e9f);
        float sv0 = fmaf(c0, -1.1920929e-8f, sc0); // exponent term + score base
        float sv1 = fmaf(c1, -1.1920929e-8f, sc1);
        uint64_t mp = pk(m0, m1);
        uint64_t r  = fma2(mp, H3, H2);
        r           = fma2(mp, r, H1);
        float r0, r1; upk(r, r0, r1);
        float s0 = fmaf(m0, r0, sv0);              // full log2-score
        float s1 = fmaf(m1, r1, sv1);
        float w0 = ex2_approx(s0);                 // MUFU
        float w1 = ex2_approx(s1);
        aB0 += w0;
        aB1 += w1;
        aA0 = fmaf(x0, w0, aA0);
        aA1 = fmaf(x1, w1, aA1);
    };

    // 78 full iterations per warp (chunks 0..2495), prefetch depth 2.
    float4 A0 = __ldcs(&ug4[lane]);
    float4 C0 = cg4[lane];
    float4 A1 = __ldcs(&ug4[lane + 32]);
    float4 C1 = cg4[lane + 32];
    int j = lane;
    #pragma unroll 2
    for (int it = 0; it < 76; ++it) {
        float4 An = __ldcs(&ug4[j + 64]);   // prefetch it+2 (~150cyc early)
        float4 Cn = cg4[j + 64];
        float4 X  = xs4[j];                 // one LDS.128
        pbody(A0.x, A0.y, C0.x, C0.y, X.x, X.y);
        pbody(A0.z, A0.w, C0.z, C0.w, X.z, X.w);
        A0 = A1; C0 = C1; A1 = An; C1 = Cn;
        j += 32;
    }
    // Pipeline epilogue: consume the two buffered iterations
    {
        float4 X = xs4[j];
        pbody(A0.x, A0.y, C0.x, C0.y, X.x, X.y);
        pbody(A0.z, A0.w, C0.z, C0.w, X.z, X.w);
        j += 32;
        X = xs4[j];
        pbody(A1.x, A1.y, C1.x, C1.y, X.x, X.y);
        pbody(A1.z, A1.w, C1.z, C1.w, X.z, X.w);
    }
    // Tail: chunks 2496..2499 handled by lanes 0..3
    if (lane < I4_ - 2496) {
        int jt = 2496 + lane;
        float4 uu = __ldcs(&ug4[jt]);
        float4 cc = cg4[jt];
        float4 X  = xs4[jt];
        pbody(uu.x, uu.y, cc.x, cc.y, X.x, X.y);
        pbody(uu.z, uu.w, cc.z, cc.w, X.z, X.w);
    }

    // Collapse scalar accumulators, then warp reduction
    float accA = aA0 + aA1;
    float accB = aB0 + aB1;
    #pragma unroll
    for (int off = 16; off > 0; off >>= 1) {
        accA += __shfl_down_sync(0xffffffffu, accA, off);
        accB += __shfl_down_sync(0xffffffffu, accB, off);
    }
    if (lane == 0) {
        out[(size_t)n * K_ + k] = accA / accB;
    }
}

extern "C" void kernel_launch(void* const* d_in, const int* in_sizes, int n_in,
                              void* d_out, int out_size) {
    const float* x      = (const float*)d_in[0];   // (1024, 10000)
    const float* u      = (const float*)d_in[1];   // (1024, 32, 10000)
    const float* logits = (const float*)d_in[2];   // (32, 10000)
    float* out = (float*)d_out;                    // (1024, 32)
    (void)in_sizes; (void)n_in; (void)out_size;

    // Stage 1: fold logits scaling + all additive constants into g_sc
    precompute_sc_kernel<<<(K_ * I_ / 4 + 255) / 256, 256>>>(logits);
    // Stage 2: main reduction
    concrete_selector_kernel<<<N_, 1024>>>(x, u, out);
}

// round 8
// speedup vs baseline: 1.7121x; 1.0072x over previous
#include <cuda_runtime.h>
#include <cstdint>

// Problem constants
static constexpr int N_ = 1024;
static constexpr int K_ = 32;
static constexpr int I_ = 10000;
static constexpr int I4_ = I_ / 4;       // 2500 float4 chunks per row

static constexpr float CS_  = 0.43280850f;     // 3/(10*ln2)
// CB3 = 51.2 (f-rebase: 2^23*512*2^-23*0.1) + 38.3 (biased-exp consts)
//     + 0.0528766 (-0.1*log2(ln2)) + 0.1135508 (poly H0)
static constexpr float CB3_ = 89.6664274f;

// Precomputed per-(k,i) score base: sc = CS*logits + CB3  (1.28 MB, L2-resident)
__device__ float g_sc[K_ * I_];

__device__ __forceinline__ float lg2_approx(float v) {
    float r; asm("lg2.approx.f32 %0, %1;" : "=f"(r) : "f"(v)); return r;
}
__device__ __forceinline__ float ex2_approx(float v) {
    float r; asm("ex2.approx.f32 %0, %1;" : "=f"(r) : "f"(v)); return r;
}
// f32x2 packed helpers (sm_103a FFMA2 path — ptxas never emits these from C++)
__device__ __forceinline__ uint64_t pk(float lo, float hi) {
    uint64_t r; asm("mov.b64 %0, {%1, %2};" : "=l"(r) : "f"(lo), "f"(hi)); return r;
}
__device__ __forceinline__ void upk(uint64_t v, float& lo, float& hi) {
    asm("mov.b64 {%0, %1}, %2;" : "=f"(lo), "=f"(hi) : "l"(v));
}
__device__ __forceinline__ uint64_t fma2(uint64_t a, uint64_t b, uint64_t c) {
    uint64_t d; asm("fma.rn.f32x2 %0, %1, %2, %3;" : "=l"(d) : "l"(a), "l"(b), "l"(c)); return d;
}

__global__ void precompute_sc_kernel(const float* __restrict__ logits) {
    int i = blockIdx.x * blockDim.x + threadIdx.x;
    if (i < (K_ * I_) / 4) {
        float4 v = reinterpret_cast<const float4*>(logits)[i];
        v.x = fmaf(v.x, CS_, CB3_);
        v.y = fmaf(v.y, CS_, CB3_);
        v.z = fmaf(v.z, CS_, CB3_);
        v.w = fmaf(v.w, CS_, CB3_);
        reinterpret_cast<float4*>(g_sc)[i] = v;
    }
}

// out[n,k] = (sum_i x*w) / (sum_i w),   w = 2^score,
// score = sc - 0.1*log2(-ln u) (sc holds logits term + every additive const).
//
// With L = lg2(u) (<0), b = bits(L) as u32:  b*2^-23 = 256 + (e+127) + z
// where -L = 2^e*(1+z). The XU-pipe I2F is avoided via the magic-number
// trick: f = uint_as_float((b>>9) | 0x4B000000) = 2^23 + b/512 EXACTLY
// (b>>9 always fits in 23 mantissa bits). So the exponent part of the score
// is one FFMA: f*(-0.1*512*2^-23) + sc, with the 2^23 rebase and all bias
// constants folded into sc at precompute time. The mantissa correction
// -0.1*(log2 m - (m-1)) is a packed degree-3 poly in m (H0 folded into sc).
// The unsigned IMNMX clamp (v >= 0x4B5B4000, i.e. -L >= 2^-18) guards BOTH
// lg2.approx underflow to +/-0 at u->1 AND any positive-L approx glitch.
// This keeps the XU pipe at 2 ops/elem (lg2 + ex2): the kernel was XU-bound
// at 3/elem (the I2F) through rounds 2-7 (415K cyc == measured 240us).
//
// Layout: mode-W (1 CTA x 1024 threads/SM), software-pipelined prefetch 2.
__global__ void __launch_bounds__(1024, 1)
concrete_selector_kernel(const float* __restrict__ x,
                         const float* __restrict__ u,
                         float* __restrict__ out) {
    __shared__ __align__(16) float xs[I_];   // x row for this n (40000 B)

    const int n   = blockIdx.x;
    const int tid = threadIdx.x;

    // Cooperative load of x[n, :] into shared (float4)
    {
        const float4* __restrict__ xg4 =
            reinterpret_cast<const float4*>(x + (size_t)n * I_);
        float4* xs4 = reinterpret_cast<float4*>(xs);
        for (int i = tid; i < I4_; i += 1024) xs4[i] = xg4[i];
    }
    __syncthreads();

    const int warp = tid >> 5;
    const int lane = tid & 31;
    const int k    = warp;    // 32 warps == 32 k's

    const float4* __restrict__ ug4 =
        reinterpret_cast<const float4*>(u + ((size_t)n * K_ + k) * (size_t)I_);
    const float4* __restrict__ cg4 =
        reinterpret_cast<const float4*>(g_sc + (size_t)k * I_);
    const float4* __restrict__ xs4 = reinterpret_cast<const float4*>(xs);

    // Packed deg-3 poly constants: -0.1*(log2 m - (m-1)) ~= H3 m^3+H2 m^2+H1 m (+H0 in sc)
    const uint64_t H3 = pk(-1.52368e-2f,  -1.52368e-2f);
    const uint64_t H2 = pk( 1.025445e-1f,  1.025445e-1f);
    const uint64_t H1 = pk(-2.009419e-1f, -2.009419e-1f);

    float aA0 = 0.0f, aA1 = 0.0f;   // scalar partial sums of x*w
    float aB0 = 0.0f, aB1 = 0.0f;   // scalar partial sums of w

    auto pbody = [&](float u0, float u1, float sc0, float sc1, float x0, float x1) {
        float L0 = lg2_approx(u0);                 // MUFU/XU (u<1 -> L<0)
        float L1 = lg2_approx(u1);
        unsigned b0 = __float_as_uint(L0);
        unsigned b1 = __float_as_uint(L1);
        float m0 = __int_as_float((b0 & 0x007fffffu) | 0x3f800000u);  // LOP3
        float m1 = __int_as_float((b1 & 0x007fffffu) | 0x3f800000u);
        unsigned v0 = (b0 >> 9) | 0x4B000000u;     // SHF + LOP3 (magic-number I2F)
        unsigned v1 = (b1 >> 9) | 0x4B000000u;
        v0 = v0 > 0x4B5B4000u ? v0 : 0x4B5B4000u;  // IMNMX.U32 clamp (-L >= 2^-18)
        v1 = v1 > 0x4B5B4000u ? v1 : 0x4B5B4000u;
        float f0 = __uint_as_float(v0);            // = 2^23 + b/512 exactly
        float f1 = __uint_as_float(v1);
        float sv0 = fmaf(f0, -6.1035156e-6f, sc0); // exponent term + score base
        float sv1 = fmaf(f1, -6.1035156e-6f, sc1);
        uint64_t mp = pk(m0, m1);
        uint64_t r  = fma2(mp, H3, H2);
        r           = fma2(mp, r, H1);
        float r0, r1; upk(r, r0, r1);
        float s0 = fmaf(m0, r0, sv0);              // full log2-score
        float s1 = fmaf(m1, r1, sv1);
        float w0 = ex2_approx(s0);                 // MUFU/XU
        float w1 = ex2_approx(s1);
        aB0 += w0;
        aB1 += w1;
        aA0 = fmaf(x0, w0, aA0);
        aA1 = fmaf(x1, w1, aA1);
    };

    // 78 full iterations per warp (chunks 0..2495), prefetch depth 2.
    float4 A0 = __ldcs(&ug4[lane]);
    float4 C0 = cg4[lane];
    float4 A1 = __ldcs(&ug4[lane + 32]);
    float4 C1 = cg4[lane + 32];
    int j = lane;
    #pragma unroll 2
    for (int it = 0; it < 76; ++it) {
        float4 An = __ldcs(&ug4[j + 64]);   // prefetch it+2 (~150cyc early)
        float4 Cn = cg4[j + 64];
        float4 X  = xs4[j];                 // one LDS.128
        pbody(A0.x, A0.y, C0.x, C0.y, X.x, X.y);
        pbody(A0.z, A0.w, C0.z, C0.w, X.z, X.w);
        A0 = A1; C0 = C1; A1 = An; C1 = Cn;
        j += 32;
    }
    // Pipeline epilogue: consume the two buffered iterations
    {
        float4 X = xs4[j];
        pbody(A0.x, A0.y, C0.x, C0.y, X.x, X.y);
        pbody(A0.z, A0.w, C0.z, C0.w, X.z, X.w);
        j += 32;
        X = xs4[j];
        pbody(A1.x, A1.y, C1.x, C1.y, X.x, X.y);
        pbody(A1.z, A1.w, C1.z, C1.w, X.z, X.w);
    }
    // Tail: chunks 2496..2499 handled by lanes 0..3
    if (lane < I4_ - 2496) {
        int jt = 2496 + lane;
        float4 uu = __ldcs(&ug4[jt]);
        float4 cc = cg4[jt];
        float4 X  = xs4[jt];
        pbody(uu.x, uu.y, cc.x, cc.y, X.x, X.y);
        pbody(uu.z, uu.w, cc.z, cc.w, X.z, X.w);
    }

    // Collapse scalar accumulators, then warp reduction
    float accA = aA0 + aA1;
    float accB = aB0 + aB1;
    #pragma unroll
    for (int off = 16; off > 0; off >>= 1) {
        accA += __shfl_down_sync(0xffffffffu, accA, off);
        accB += __shfl_down_sync(0xffffffffu, accB, off);
    }
    if (lane == 0) {
        out[(size_t)n * K_ + k] = accA / accB;
    }
}

extern "C" void kernel_launch(void* const* d_in, const int* in_sizes, int n_in,
                              void* d_out, int out_size) {
    const float* x      = (const float*)d_in[0];   // (1024, 10000)
    const float* u      = (const float*)d_in[1];   // (1024, 32, 10000)
    const float* logits = (const float*)d_in[2];   // (32, 10000)
    float* out = (float*)d_out;                    // (1024, 32)
    (void)in_sizes; (void)n_in; (void)out_size;

    // Stage 1: fold logits scaling + all additive constants into g_sc
    precompute_sc_kernel<<<(K_ * I_ / 4 + 255) / 256, 256>>>(logits);
    // Stage 2: main reduction
    concrete_selector_kernel<<<N_, 1024>>>(x, u, out);
}

// round 9
// speedup vs baseline: 1.8432x; 1.0766x over previous
#include <cuda_runtime.h>
#include <cstdint>

// Problem constants
static constexpr int N_ = 1024;
static constexpr int K_ = 32;
static constexpr int I_ = 10000;
static constexpr int I4_ = I_ / 4;       // 2500 float4 chunks per row

static constexpr float CS_  = 0.43280850f;     // 3/(10*ln2)
// CB3 = 51.2+25.6+12.7 (magic-number rebase + exp-bias consts)
//     + 0.0528766 (-0.1*log2(ln2)) + 0.1135508 (poly H0)
static constexpr float CB3_ = 89.6664274f;

// Precomputed per-(k,i) score base: sc = CS*logits + CB3  (1.28 MB, L2-resident)
__device__ float g_sc[K_ * I_];

__device__ __forceinline__ float lg2_approx(float v) {
    float r; asm("lg2.approx.f32 %0, %1;" : "=f"(r) : "f"(v)); return r;
}
__device__ __forceinline__ float ex2_approx(float v) {
    float r; asm("ex2.approx.f32 %0, %1;" : "=f"(r) : "f"(v)); return r;
}
// f32x2 packed helpers (sm_103a FFMA2 path — ptxas never emits these from C++)
__device__ __forceinline__ uint64_t pk(float lo, float hi) {
    uint64_t r; asm("mov.b64 %0, {%1, %2};" : "=l"(r) : "f"(lo), "f"(hi)); return r;
}
__device__ __forceinline__ void upk(uint64_t v, float& lo, float& hi) {
    asm("mov.b64 {%0, %1}, %2;" : "=f"(lo), "=f"(hi) : "l"(v));
}
__device__ __forceinline__ uint64_t fma2(uint64_t a, uint64_t b, uint64_t c) {
    uint64_t d; asm("fma.rn.f32x2 %0, %1, %2, %3;" : "=l"(d) : "l"(a), "l"(b), "l"(c)); return d;
}
__device__ __forceinline__ uint64_t add2(uint64_t a, uint64_t b) {
    uint64_t d; asm("add.rn.f32x2 %0, %1, %2;" : "=l"(d) : "l"(a), "l"(b)); return d;
}

__global__ void precompute_sc_kernel(const float* __restrict__ logits) {
    int i = blockIdx.x * blockDim.x + threadIdx.x;
    if (i < (K_ * I_) / 4) {
        float4 v = reinterpret_cast<const float4*>(logits)[i];
        v.x = fmaf(v.x, CS_, CB3_);
        v.y = fmaf(v.y, CS_, CB3_);
        v.z = fmaf(v.z, CS_, CB3_);
        v.w = fmaf(v.w, CS_, CB3_);
        reinterpret_cast<float4*>(g_sc)[i] = v;
    }
}

// out[n,k] = (sum_i x*w) / (sum_i w),   w = 2^score,
// score = sc - 0.1*log2(-ln u) (sc holds logits term + every additive const).
//
// With L = lg2(u) (<0), b = bits(L):  magic-number I2F avoids the XU pipe:
// f = uint_as_float((b>>9)|0x4B000000) = 2^23 + b/512 exactly, so the
// exponent part of the score is one FFMA (rebase consts folded into sc).
// Mantissa correction -0.1*(log2 m - (m-1)) is a packed degree-3 poly.
// Clamp directly on b (IMNMX.U32, b >= 0xB2000000 i.e. -L >= 2^-27): caps
// w at ~6.75 only where lg2.approx underflows to +/-0 (u==1ulp-below-1 or
// u==0's -inf path is untouched); also subsumes positive-L approx glitches.
// At the clamp value the mantissa is exactly 1.0 so the poly term cancels.
//
// Layout: mode-W (1 CTA x 1024 threads/SM). Main loop is a zero-rotation
// ping-pong pipeline: buffers P and Q are each consumed and then refilled
// IN PLACE from 2 iterations ahead — no inter-buffer register moves (the
// rotating version left ~16 MOVs/iter in SASS, ~4 issues/elem of pure waste).
__global__ void __launch_bounds__(1024, 1)
concrete_selector_kernel(const float* __restrict__ x,
                         const float* __restrict__ u,
                         float* __restrict__ out) {
    __shared__ __align__(16) float xs[I_];   // x row for this n (40000 B)

    const int n   = blockIdx.x;
    const int tid = threadIdx.x;

    // Cooperative load of x[n, :] into shared (float4)
    {
        const float4* __restrict__ xg4 =
            reinterpret_cast<const float4*>(x + (size_t)n * I_);
        float4* xs4 = reinterpret_cast<float4*>(xs);
        for (int i = tid; i < I4_; i += 1024) xs4[i] = xg4[i];
    }
    __syncthreads();

    const int warp = tid >> 5;
    const int lane = tid & 31;
    const int k    = warp;    // 32 warps == 32 k's

    const float4* __restrict__ ug4 =
        reinterpret_cast<const float4*>(u + ((size_t)n * K_ + k) * (size_t)I_);
    const float4* __restrict__ cg4 =
        reinterpret_cast<const float4*>(g_sc + (size_t)k * I_);
    const ulonglong2* __restrict__ xsv =
        reinterpret_cast<const ulonglong2*>(xs);   // LDS.128 -> two packed pairs

    // Packed deg-3 poly: -0.1*(log2 m-(m-1)) ~= H3 m^3+H2 m^2+H1 m (+H0 in sc)
    const uint64_t H3 = pk(-1.52368e-2f,  -1.52368e-2f);
    const uint64_t H2 = pk( 1.025445e-1f,  1.025445e-1f);
    const uint64_t H1 = pk(-2.009419e-1f, -2.009419e-1f);

    uint64_t accA2 = 0;   // packed pair of partial sums of x*w
    uint64_t accB2 = 0;   // packed pair of partial sums of w

    auto ppair = [&](float u0, float u1, float sc0, float sc1, uint64_t xp) {
        float L0 = lg2_approx(u0);                 // XU (u<1 -> L<0)
        float L1 = lg2_approx(u1);
        unsigned b0 = __float_as_uint(L0);
        unsigned b1 = __float_as_uint(L1);
        b0 = b0 > 0xB2000000u ? b0 : 0xB2000000u;  // IMNMX.U32: -L >= 2^-27
        b1 = b1 > 0xB2000000u ? b1 : 0xB2000000u;
        float m0 = __int_as_float((b0 & 0x007fffffu) | 0x3f800000u);  // LOP3
        float m1 = __int_as_float((b1 & 0x007fffffu) | 0x3f800000u);
        float f0 = __uint_as_float((b0 >> 9) | 0x4B000000u);  // SHF+LOP3
        float f1 = __uint_as_float((b1 >> 9) | 0x4B000000u);
        float sv0 = fmaf(f0, -6.1035156e-6f, sc0); // exponent term + score base
        float sv1 = fmaf(f1, -6.1035156e-6f, sc1);
        uint64_t mp = pk(m0, m1);
        uint64_t r  = fma2(mp, H3, H2);
        r           = fma2(mp, r, H1);
        uint64_t s2 = fma2(mp, r, pk(sv0, sv1));   // full log2-score (pair)
        float s0, s1; upk(s2, s0, s1);
        uint64_t wp = pk(ex2_approx(s0), ex2_approx(s1));   // XU x2
        accB2 = add2(accB2, wp);
        accA2 = fma2(xp, wp, accA2);
    };

    // 78 iterations per warp (chunks 0..2495). Ping-pong, prefetch distance 2:
    // the loop body consumes P (chunk j) then refills P from chunk j+64, then
    // consumes Q (j+32) and refills Q from j+96. No buffer rotation.
    float4 PA = __ldcs(&ug4[lane]);
    float4 PC = cg4[lane];
    float4 QA = __ldcs(&ug4[lane + 32]);
    float4 QC = cg4[lane + 32];
    int j = lane;
    for (int it = 0; it < 38; ++it) {    // 38 * 2 = iterations 0..75
        ulonglong2 X = xsv[j];
        ppair(PA.x, PA.y, PC.x, PC.y, X.x);
        ppair(PA.z, PA.w, PC.z, PC.w, X.y);
        PA = __ldcs(&ug4[j + 64]);       // refill P for iteration it*2+2
        PC = cg4[j + 64];
        ulonglong2 X2 = xsv[j + 32];
        ppair(QA.x, QA.y, QC.x, QC.y, X2.x);
        ppair(QA.z, QA.w, QC.z, QC.w, X2.y);
        QA = __ldcs(&ug4[j + 96]);       // refill Q for iteration it*2+3
        QC = cg4[j + 96];
        j += 64;
    }
    // Epilogue: iterations 76, 77 are resident in P and Q (j = lane+2432)
    {
        ulonglong2 X = xsv[j];
        ppair(PA.x, PA.y, PC.x, PC.y, X.x);
        ppair(PA.z, PA.w, PC.z, PC.w, X.y);
        ulonglong2 X2 = xsv[j + 32];
        ppair(QA.x, QA.y, QC.x, QC.y, X2.x);
        ppair(QA.z, QA.w, QC.z, QC.w, X2.y);
    }
    // Tail: chunks 2496..2499 handled by lanes 0..3
    if (lane < I4_ - 2496) {
        int jt = 2496 + lane;
        float4 uu = __ldcs(&ug4[jt]);
        float4 cc = cg4[jt];
        ulonglong2 X = xsv[jt];
        ppair(uu.x, uu.y, cc.x, cc.y, X.x);
        ppair(uu.z, uu.w, cc.z, cc.w, X.y);
    }

    // Collapse packed accumulators, then warp reduction
    float a0, a1, bb0, bb1;
    upk(accA2, a0, a1);
    upk(accB2, bb0, bb1);
    float accA = a0 + a1;
    float accB = bb0 + bb1;
    #pragma unroll
    for (int off = 16; off > 0; off >>= 1) {
        accA += __shfl_down_sync(0xffffffffu, accA, off);
        accB += __shfl_down_sync(0xffffffffu, accB, off);
    }
    if (lane == 0) {
        out[(size_t)n * K_ + k] = accA / accB;
    }
}

extern "C" void kernel_launch(void* const* d_in, const int* in_sizes, int n_in,
                              void* d_out, int out_size) {
    const float* x      = (const float*)d_in[0];   // (1024, 10000)
    const float* u      = (const float*)d_in[1];   // (1024, 32, 10000)
    const float* logits = (const float*)d_in[2];   // (32, 10000)
    float* out = (float*)d_out;                    // (1024, 32)
    (void)in_sizes; (void)n_in; (void)out_size;

    // Stage 1: fold logits scaling + all additive constants into g_sc
    precompute_sc_kernel<<<(K_ * I_ / 4 + 255) / 256, 256>>>(logits);
    // Stage 2: main reduction
    concrete_selector_kernel<<<N_, 1024>>>(x, u, out);
}